// round 10
// baseline (speedup 1.0000x reference)
#include <cuda_runtime.h>
#include <cuda_bf16.h>
#include <cstdint>
#include <math.h>

#define NPTS    524288
#define NGRIDS  64
#define GVOX    262144      /* 64^3 */
#define PE_L    6
#define NBUCK   4096
#define THREADS 256
#define PTS_CTA 128

// x-duplicated channel-interleaved volumes (256 MB)
__device__ float4 g_dupx[NGRIDS * GVOX];
__device__ int    g_hist[NBUCK];
__device__ int    g_off[NBUCK];
__device__ int    g_perm[NPTS];

// ---------------- packed f32x2 helpers ----------------
__device__ __forceinline__ void fma2(unsigned long long& d,
                                     unsigned long long a,
                                     unsigned long long b) {
    asm("fma.rn.f32x2 %0, %1, %2, %0;" : "+l"(d) : "l"(a), "l"(b));
}
__device__ __forceinline__ unsigned long long bcast2(float f) {
    unsigned long long r;
    asm("mov.b64 %0, {%1, %2};" : "=l"(r) : "f"(f), "f"(f));
    return r;
}
__device__ __forceinline__ float2 unpack2(unsigned long long v) {
    float2 f;
    asm("mov.b64 {%0, %1}, %2;" : "=f"(f.x), "=f"(f.y) : "l"(v));
    return f;
}
// acc[0..15] += f * row32[0..31]  (half-row, smem broadcast)
__device__ __forceinline__ void accum_half(unsigned long long* acc,
                                           const float* row32, float f) {
    unsigned long long ff = bcast2(f);
    const ulonglong2* r2 = reinterpret_cast<const ulonglong2*>(row32);
#pragma unroll
    for (int i = 0; i < 8; i++) {
        ulonglong2 w = r2[i];
        fma2(acc[2 * i], ff, w.x);
        fma2(acc[2 * i + 1], ff, w.y);
    }
}
__device__ __forceinline__ float snakef(float h) {
    float s = __sinf(h);
    return fmaf(0.5f, h, s * s);
}
__device__ __forceinline__ int bucket_key(float px, float py, float pz) {
    int qx = min(max((int)((px + 1.f) * 8.f), 0), 15);
    int qy = min(max((int)((py + 1.f) * 8.f), 0), 15);
    int qz = min(max((int)((pz + 1.f) * 8.f), 0), 15);
    return (qx << 8) | (qy << 4) | qz;
}

// ---------------- repack + sort pipeline (unchanged from R8) ----------------
__global__ void repack_dup(const float* __restrict__ fg) {
    int idx = blockIdx.x * blockDim.x + threadIdx.x;
    int g = idx >> 16;
    int v4 = (idx & 65535) << 2;
    const float* f0p = fg + (size_t)(2 * g) * GVOX;
    const float* f1p = fg + (size_t)(2 * g + 1) * GVOX;
    float4 a = *(const float4*)(f0p + v4);
    float4 b = *(const float4*)(f1p + v4);
    float a4, b4;
    if ((v4 & 63) == 60) { a4 = a.w; b4 = b.w; }
    else                 { a4 = f0p[v4 + 4]; b4 = f1p[v4 + 4]; }
    float4* o = g_dupx + ((size_t)g << 18) + v4;
    o[0] = make_float4(a.x, b.x, a.y, b.y);
    o[1] = make_float4(a.y, b.y, a.z, b.z);
    o[2] = make_float4(a.z, b.z, a.w, b.w);
    o[3] = make_float4(a.w, b.w, a4, b4);
}
__global__ void zero_hist() {
    g_hist[blockIdx.x * blockDim.x + threadIdx.x] = 0;
}
__global__ void hist_kernel(const float* __restrict__ x) {
    int pt = blockIdx.x * blockDim.x + threadIdx.x;
    int k = bucket_key(x[3 * pt], x[3 * pt + 1], x[3 * pt + 2]);
    atomicAdd(&g_hist[k], 1);
}
__global__ void scan_hist() {
    __shared__ int s[1024];
    int t = threadIdx.x;
    int base = t * 4;
    int a0 = g_hist[base], a1 = g_hist[base + 1], a2 = g_hist[base + 2],
        a3 = g_hist[base + 3];
    int sum = a0 + a1 + a2 + a3;
    s[t] = sum;
    __syncthreads();
    for (int d = 1; d < 1024; d <<= 1) {
        int v = (t >= d) ? s[t - d] : 0;
        __syncthreads();
        s[t] += v;
        __syncthreads();
    }
    int excl = s[t] - sum;
    g_off[base] = excl;
    g_off[base + 1] = excl + a0;
    g_off[base + 2] = excl + a0 + a1;
    g_off[base + 3] = excl + a0 + a1 + a2;
}
__global__ void scatter_kernel(const float* __restrict__ x) {
    int pt = blockIdx.x * blockDim.x + threadIdx.x;
    int k = bucket_key(x[3 * pt], x[3 * pt + 1], x[3 * pt + 2]);
    int pos = atomicAdd(&g_off[k], 1);
    g_perm[pos] = pt;
}

// ---------------- smem layout (bytes) ----------------
#define SM_PE    0            /* 36*64 f32 = 9216                          */
#define SM_W0G   9216         /* 64*132 f32 = 33792; reused as H0 (128*65) */
#define SM_W1    43008        /* 64*64 f32 = 16384 (original [j][k])       */
#define SM_GP    59392        /* 64*8 f32 = 2048                           */
#define SM_AUX   61440        /* b0[64] b1[64] w2[64] = 768                */
#define SM_PART  62208        /* 128 f32 partials = 512                    */
#define SMEM_TOTAL 62720

__global__ void __launch_bounds__(THREADS, 3)
amrsrn_main(const float* __restrict__ x,
            const float* __restrict__ gscale,
            const float* __restrict__ gtrans,
            const float* __restrict__ W0,
            const float* __restrict__ b0,
            const float* __restrict__ W1,
            const float* __restrict__ b1,
            const float* __restrict__ W2,
            const float* __restrict__ b2,
            float* __restrict__ out) {
    extern __shared__ char smem[];
    float* smf = (float*)smem;
    float* auxf = smf + SM_AUX / 4;
    const int tid = threadIdx.x;
    const int p_local = tid & 127;
    const int half = tid >> 7;      // warp-uniform: warps 0-3 half0, 4-7 half1
    const int hoff = half * 32;

    // ---- stage weights ----
    for (int i = tid; i < 36 * 64; i += THREADS)
        smf[SM_PE / 4 + i] = W0[i];
    for (int i = tid; i < 64 * 128; i += THREADS) {
        int g = i >> 7, j = i & 127;
        int row = 36 + 2 * g + (j >> 6);
        smf[SM_W0G / 4 + g * 132 + j] = W0[row * 64 + (j & 63)];
    }
    for (int i = tid; i < 64 * 64; i += THREADS)
        smf[SM_W1 / 4 + i] = W1[i];                 // keep [j][k] layout
    for (int i = tid; i < 64; i += THREADS) {
        auxf[i] = b0[i];
        auxf[64 + i] = b1[i];
        auxf[128 + i] = W2[i];
    }
    for (int i = tid; i < 64; i += THREADS) {
        smf[SM_GP / 4 + i * 8 + 0] = gscale[3 * i + 0];
        smf[SM_GP / 4 + i * 8 + 1] = gscale[3 * i + 1];
        smf[SM_GP / 4 + i * 8 + 2] = gscale[3 * i + 2];
        smf[SM_GP / 4 + i * 8 + 3] = gtrans[3 * i + 0];
        smf[SM_GP / 4 + i * 8 + 4] = gtrans[3 * i + 1];
        smf[SM_GP / 4 + i * 8 + 5] = gtrans[3 * i + 2];
        smf[SM_GP / 4 + i * 8 + 6] = 0.f;
        smf[SM_GP / 4 + i * 8 + 7] = 0.f;
    }
    __syncthreads();

    const int pt = g_perm[blockIdx.x * PTS_CTA + p_local];
    const float px = __ldg(&x[3 * pt + 0]);
    const float py = __ldg(&x[3 * pt + 1]);
    const float pz = __ldg(&x[3 * pt + 2]);
    const float xyz[3] = {px, py, pz};
    const float4* gp4 = (const float4*)(smem + SM_GP);

    // ---- half h0 accumulators (16 packed f32x2), init = b0 half ----
    unsigned long long acc[16];
    const unsigned long long* pb0 = (const unsigned long long*)&auxf[hoff];
#pragma unroll
    for (int i = 0; i < 16; i++) acc[i] = pb0[i];

    // ---- PE via double-angle recurrence (broadcast half-rows) ----
#pragma unroll
    for (int d = 0; d < 3; d++) {
        float s, c;
        sincosf(xyz[d] * 3.14159265358979323846f, &s, &c);
#pragma unroll
        for (int l = 0; l < PE_L; l++) {
            accum_half(acc, &smf[SM_PE / 4 + (l * 3 + d) * 64 + hoff], s);
            accum_half(acc, &smf[SM_PE / 4 + (18 + l * 3 + d) * 64 + hoff], c);
            float s2 = 2.f * s * c;
            float c2 = fmaf(-2.f * s, s, 1.f);
            s = s2;
            c = c2;
        }
    }

    // ---- validity mask ----
    unsigned long long mask = 0ull;
#pragma unroll 1
    for (int g = 0; g < 64; g++) {
        float4 p1 = gp4[g * 2];
        float4 p2 = gp4[g * 2 + 1];
        float ix = fmaf(fmaf(px, p1.x, p1.w), 31.5f, 31.5f);
        float iy = fmaf(fmaf(py, p1.y, p2.x), 31.5f, 31.5f);
        float iz = fmaf(fmaf(pz, p1.z, p2.y), 31.5f, 31.5f);
        if (ix > -1.f && ix < 64.f && iy > -1.f && iy < 64.f && iz > -1.f &&
            iz < 64.f)
            mask |= 1ull << g;
    }

    // ---- compacted sparse gather + half accumulation ----
    while (mask) {
        int g = __ffsll((long long)mask) - 1;
        mask &= mask - 1;
        float4 p1 = gp4[g * 2];
        float4 p2 = gp4[g * 2 + 1];
        float ix = fmaf(fmaf(px, p1.x, p1.w), 31.5f, 31.5f);
        float iy = fmaf(fmaf(py, p1.y, p2.x), 31.5f, 31.5f);
        float iz = fmaf(fmaf(pz, p1.z, p2.y), 31.5f, 31.5f);
        float fx = floorf(ix), fy = floorf(iy), fz = floorf(iz);
        int X0 = (int)fx, Y0 = (int)fy, Z0 = (int)fz;
        float wx1 = ix - fx, wy1 = iy - fy, wz1 = iz - fz;
        float wx0 = 1.f - wx1, wy0 = 1.f - wy1, wz0 = 1.f - wz1;
        int bx = X0;
        float wa = wx0, wb = wx1;
        if (X0 < 0)        { bx = 0; wa = wx1; wb = 0.f; }
        else if (X0 >= 63) { wb = 0.f; }
        if (Y0 < 0)   wy0 = 0.f;
        if (Y0 >= 63) wy1 = 0.f;
        if (Z0 < 0)   wz0 = 0.f;
        if (Z0 >= 63) wz1 = 0.f;
        int y0c = max(Y0, 0), y1c = min(Y0 + 1, 63);
        int z0c = max(Z0, 0), z1c = min(Z0 + 1, 63);

        const float4* vol = g_dupx + ((size_t)g << 18);
        float4 q00 = __ldg(&vol[(z0c << 12) + (y0c << 6) + bx]);
        float4 q01 = __ldg(&vol[(z0c << 12) + (y1c << 6) + bx]);
        float4 q10 = __ldg(&vol[(z1c << 12) + (y0c << 6) + bx]);
        float4 q11 = __ldg(&vol[(z1c << 12) + (y1c << 6) + bx]);

        float w00 = wz0 * wy0, w01 = wz0 * wy1;
        float w10 = wz1 * wy0, w11 = wz1 * wy1;

        float r00 = fmaf(wb, q00.z, wa * q00.x);
        float r01 = fmaf(wb, q01.z, wa * q01.x);
        float r10 = fmaf(wb, q10.z, wa * q10.x);
        float r11 = fmaf(wb, q11.z, wa * q11.x);
        float f0 = w00 * r00;
        f0 = fmaf(w01, r01, f0);
        f0 = fmaf(w10, r10, f0);
        f0 = fmaf(w11, r11, f0);

        float s00 = fmaf(wb, q00.w, wa * q00.y);
        float s01 = fmaf(wb, q01.w, wa * q01.y);
        float s10 = fmaf(wb, q10.w, wa * q10.y);
        float s11 = fmaf(wb, q11.w, wa * q11.y);
        float f1 = w00 * s00;
        f1 = fmaf(w01, s01, f1);
        f1 = fmaf(w10, s10, f1);
        f1 = fmaf(w11, s11, f1);

        const float* wrow = &smf[SM_W0G / 4 + g * 132 + hoff];
        accum_half(acc, wrow, f0);
        accum_half(acc, wrow + 64, f1);
    }

    // ---- all gathers done; reuse W0G region as H0 [128][65] ----
    __syncthreads();
    float* H0 = smf + SM_W0G / 4;
    {
        float* dst = &H0[p_local * 65 + hoff];
#pragma unroll
        for (int i = 0; i < 16; i++) {
            float2 h = unpack2(acc[i]);
            dst[2 * i] = snakef(h.x);
            dst[2 * i + 1] = snakef(h.y);
        }
    }
    __syncthreads();

    // ---- layer 1: this thread computes h1[k] for k in [hoff, hoff+32) ----
    unsigned long long h1[16];
    const unsigned long long* pb1 = (const unsigned long long*)&auxf[64 + hoff];
#pragma unroll
    for (int i = 0; i < 16; i++) h1[i] = pb1[i];
    const float* W1s = smf + SM_W1 / 4;
    const float* h0row = &H0[p_local * 65];
#pragma unroll 4
    for (int j = 0; j < 64; j++) {
        float a = h0row[j];
        accum_half(h1, &W1s[j * 64 + hoff], a);
    }

    // ---- epilogue: snake + dot with W2 half, combine halves via smem ----
    float part = 0.f;
#pragma unroll
    for (int i = 0; i < 16; i++) {
        float2 h = unpack2(h1[i]);
        part = fmaf(snakef(h.x), auxf[128 + hoff + 2 * i], part);
        part = fmaf(snakef(h.y), auxf[128 + hoff + 2 * i + 1], part);
    }
    float* PART = smf + SM_PART / 4;
    if (half == 0) PART[p_local] = part;
    __syncthreads();
    if (half == 1) out[pt] = part + PART[p_local] + __ldg(b2);
}

extern "C" void kernel_launch(void* const* d_in, const int* in_sizes, int n_in,
                              void* d_out, int out_size) {
    const float* x      = (const float*)d_in[0];
    const float* gsc    = (const float*)d_in[1];
    const float* gtr    = (const float*)d_in[2];
    const float* fgrids = (const float*)d_in[3];
    const float* W0     = (const float*)d_in[4];
    const float* b0     = (const float*)d_in[5];
    const float* W1     = (const float*)d_in[6];
    const float* b1     = (const float*)d_in[7];
    const float* W2     = (const float*)d_in[8];
    const float* b2     = (const float*)d_in[9];
    float* out          = (float*)d_out;

    cudaFuncSetAttribute(amrsrn_main,
                         cudaFuncAttributeMaxDynamicSharedMemorySize,
                         SMEM_TOTAL);

    repack_dup<<<(NGRIDS * GVOX / 4) / 256, 256>>>(fgrids);
    zero_hist<<<16, 256>>>();
    hist_kernel<<<NPTS / 256, 256>>>(x);
    scan_hist<<<1, 1024>>>();
    scatter_kernel<<<NPTS / 256, 256>>>(x);
    amrsrn_main<<<NPTS / PTS_CTA, THREADS, SMEM_TOTAL>>>(x, gsc, gtr, W0, b0,
                                                         W1, b1, W2, b2, out);
}